// round 16
// baseline (speedup 1.0000x reference)
#include <cuda_runtime.h>
#include <math.h>

#define B 8
#define N 2048
#define FIN 128
#define FOUT 64
#define ALPHA 0.2f

#define TI 64
#define TJ 64
#define SPLIT 2
#define JTILES ((N / SPLIT) / TJ)   // 16

typedef unsigned long long u64;

// Scratch (allocation-free rule: device globals)
__device__ float g_wh[B * N * FOUT];                 // 4 MB
__device__ float g_s1[B * N];
__device__ float g_s2[B * N];
__device__ float g_acc[SPLIT * B * N * FOUT];        // 8 MB partials
__device__ float g_l[SPLIT * B * N];                 // partial row sums

__device__ __forceinline__ u64 bcast2(float v) {
    u64 r;
    asm("mov.b64 %0, {%1, %1};" : "=l"(r) : "r"(__float_as_uint(v)));
    return r;
}
__device__ __forceinline__ u64 pack2(float a, float b) {
    u64 r;
    asm("mov.b64 %0, {%1, %2};" : "=l"(r) : "r"(__float_as_uint(a)), "r"(__float_as_uint(b)));
    return r;
}
__device__ __forceinline__ void fma2(u64& acc, u64 a, u64 b) {
    asm("fma.rn.f32x2 %0, %1, %2, %0;" : "+l"(acc) : "l"(a), "l"(b));
}
__device__ __forceinline__ void add2(u64& acc, u64 a) {
    asm("add.rn.f32x2 %0, %1, %0;" : "+l"(acc) : "l"(a));
}
__device__ __forceinline__ float lo2(u64 v) { return __uint_as_float((unsigned)(v & 0xffffffffu)); }
__device__ __forceinline__ float hi2(u64 v) { return __uint_as_float((unsigned)(v >> 32)); }

// ---------------------------------------------------------------------------
// K1: wh = x @ W ; s1 = wh @ a1 ; s2 = wh @ a2.
// Block: 256 threads, 32 rows. W staged in smem (32 KB), x via broadcast LDG.
// Thread (r = t>>3, cg = t&7) owns cols [cg*4, cg*4+4) and [32+cg*4, ...+4).
// ---------------------------------------------------------------------------
__global__ __launch_bounds__(256) void k1_proj(const float* __restrict__ x,
                                               const float* __restrict__ W,
                                               const float* __restrict__ w2) {
    __shared__ __align__(16) float Ws[FIN][FOUT];    // 32 KB
    int t = threadIdx.x;

#pragma unroll
    for (int q = 0; q < 8; ++q) {
        int lin = t + q * 256;                       // 2048 float4s
        ((float4*)Ws)[lin] = ((const float4*)W)[lin];
    }
    __syncthreads();

    int r = t >> 3, cg = t & 7;
    int row = blockIdx.x * 32 + r;
    int c1 = cg * 4, c2 = 32 + cg * 4;
    const float4* xr = (const float4*)(x + (size_t)row * FIN);

    u64 acc[4] = {0ull, 0ull, 0ull, 0ull};
#pragma unroll 8
    for (int kc = 0; kc < FIN / 4; ++kc) {
        float4 xq = __ldg(&xr[kc]);
        float xv[4] = {xq.x, xq.y, xq.z, xq.w};
#pragma unroll
        for (int q = 0; q < 4; ++q) {
            int k = kc * 4 + q;
            u64 xx = bcast2(xv[q]);
            ulonglong2 wa = *(const ulonglong2*)&Ws[k][c1];
            ulonglong2 wb = *(const ulonglong2*)&Ws[k][c2];
            fma2(acc[0], wa.x, xx); fma2(acc[1], wa.y, xx);
            fma2(acc[2], wb.x, xx); fma2(acc[3], wb.y, xx);
        }
    }

    float wv[8];
    wv[0] = lo2(acc[0]); wv[1] = hi2(acc[0]); wv[2] = lo2(acc[1]); wv[3] = hi2(acc[1]);
    wv[4] = lo2(acc[2]); wv[5] = hi2(acc[2]); wv[6] = lo2(acc[3]); wv[7] = hi2(acc[3]);

    *(float4*)&g_wh[(size_t)row * FOUT + c1] = make_float4(wv[0], wv[1], wv[2], wv[3]);
    *(float4*)&g_wh[(size_t)row * FOUT + c2] = make_float4(wv[4], wv[5], wv[6], wv[7]);

    float4 a1a = *(const float4*)&w2[c1];
    float4 a1b = *(const float4*)&w2[c2];
    float4 a2a = *(const float4*)&w2[FOUT + c1];
    float4 a2b = *(const float4*)&w2[FOUT + c2];
    float p1 = wv[0]*a1a.x + wv[1]*a1a.y + wv[2]*a1a.z + wv[3]*a1a.w
             + wv[4]*a1b.x + wv[5]*a1b.y + wv[6]*a1b.z + wv[7]*a1b.w;
    float p2 = wv[0]*a2a.x + wv[1]*a2a.y + wv[2]*a2a.z + wv[3]*a2a.w
             + wv[4]*a2b.x + wv[5]*a2b.y + wv[6]*a2b.z + wv[7]*a2b.w;
#pragma unroll
    for (int off = 4; off > 0; off >>= 1) {
        p1 += __shfl_xor_sync(0xffffffffu, p1, off);
        p2 += __shfl_xor_sync(0xffffffffu, p2, off);
    }
    if (cg == 0) { g_s1[row] = p1; g_s2[row] = p2; }
}

// ---------------------------------------------------------------------------
// K2: fused flash-GAT. Unnormalized p = mask * exp(leakyrelu(s1_i + s2_j))
// (bounded, no max-subtraction needed). Accumulates acc = sum p*wh and
// l = sum p in one adj pass. Grid split over j (SPLIT partials).
// Block: 64 i-rows, 256 threads; thread = 2 rows x (4+4 cols).
// ---------------------------------------------------------------------------
__global__ __launch_bounds__(256) void k2_attn(const int* __restrict__ adj) {
    __shared__ __align__(16) float wh_s[TJ][68];     // 16B-aligned rows, 1-wf reads
    __shared__ __align__(16) float p_s[TJ][66];      // [j][i], float2 reads
    __shared__ float s1_s[TI];
    __shared__ float s2_s[TJ];

    int t = threadIdx.x;
    int b = blockIdx.y;
    int i0 = blockIdx.x * TI;
    int z = blockIdx.z;
    int jbase = z * (N / SPLIT);

    const int* adjb = adj + (size_t)b * N * N;
    const float* whb = g_wh + (size_t)b * N * FOUT;

    int cg = t & 7, rg = t >> 3;
    int c1 = cg * 4, c2 = 32 + cg * 4;
    int iq = t >> 6, jq = t & 63;

    if (t < TI) s1_s[t] = g_s1[b * N + i0 + t];

    u64 acc[2][4];
#pragma unroll
    for (int r = 0; r < 2; ++r)
#pragma unroll
        for (int q = 0; q < 4; ++q) acc[r][q] = 0ull;
    u64 lacc = 0ull;

    // adj software prefetch: 16 rows for this thread's (iq, jq) column
    const int* aptr = adjb + (size_t)(i0 + iq * 16) * N + jbase + jq;
    int areg[16];
#pragma unroll
    for (int q = 0; q < 16; ++q) areg[q] = aptr[(size_t)q * N];

    for (int jt = 0; jt < JTILES; ++jt) {
        int j0 = jbase + jt * TJ;

        __syncthreads();   // prev accumulate done; also covers s1_s on iter 0
#pragma unroll
        for (int q = 0; q < 4; ++q) {
            int lin = t + q * 256;
            int row = lin >> 4;
            int c4 = (lin & 15) * 4;
            *(float4*)&wh_s[row][c4] =
                *(const float4*)&whb[(size_t)(j0 + row) * FOUT + c4];
        }
        if (t < TJ) s2_s[t] = g_s2[b * N + j0 + t];
        __syncthreads();

        // score phase -> transposed p_s[j][i]
        float s2v = s2_s[jq];
#pragma unroll
        for (int q = 0; q < 16; ++q) {
            int i = iq * 16 + q;
            float tt = s1_s[i] + s2v;
            float lk = tt > 0.f ? tt : ALPHA * tt;
            p_s[jq][i] = (areg[q] > 0) ? __expf(lk) : 0.f;
        }

        // prefetch next tile's adj while others finish scores / we sync
        if (jt + 1 < JTILES) {
            const int* ap = aptr + (jt + 1) * TJ;
#pragma unroll
            for (int q = 0; q < 16; ++q) areg[q] = ap[(size_t)q * N];
        }
        __syncthreads();

        // accumulate: 3 smem wavefronts + 9 fma-pipe issues per j per warp
#pragma unroll 8
        for (int j = 0; j < TJ; ++j) {
            float2 p2 = *(const float2*)&p_s[j][rg * 2];
            ulonglong2 wa = *(const ulonglong2*)&wh_s[j][c1];
            ulonglong2 wb = *(const ulonglong2*)&wh_s[j][c2];
            u64 pp0 = bcast2(p2.x);
            u64 pp1 = bcast2(p2.y);
            fma2(acc[0][0], wa.x, pp0); fma2(acc[0][1], wa.y, pp0);
            fma2(acc[0][2], wb.x, pp0); fma2(acc[0][3], wb.y, pp0);
            fma2(acc[1][0], wa.x, pp1); fma2(acc[1][1], wa.y, pp1);
            fma2(acc[1][2], wb.x, pp1); fma2(acc[1][3], wb.y, pp1);
            add2(lacc, pack2(p2.x, p2.y));
        }
    }

    // epilogue: write partials
    size_t pbase = ((size_t)z * (B * N) + (size_t)b * N) * FOUT;
#pragma unroll
    for (int r = 0; r < 2; ++r) {
        int i = i0 + rg * 2 + r;
        *(float4*)&g_acc[pbase + (size_t)i * FOUT + c1] =
            make_float4(lo2(acc[r][0]), hi2(acc[r][0]), lo2(acc[r][1]), hi2(acc[r][1]));
        *(float4*)&g_acc[pbase + (size_t)i * FOUT + c2] =
            make_float4(lo2(acc[r][2]), hi2(acc[r][2]), lo2(acc[r][3]), hi2(acc[r][3]));
    }
    if (cg == 0) {
        int i = i0 + rg * 2;
        g_l[(size_t)z * (B * N) + b * N + i]     = lo2(lacc);
        g_l[(size_t)z * (B * N) + b * N + i + 1] = hi2(lacc);
    }
}

// ---------------------------------------------------------------------------
// K3: combine split partials, normalize, ELU.
// ---------------------------------------------------------------------------
#define TOT4 (B * N * FOUT / 4)   // 262144 float4s per split
__global__ __launch_bounds__(256) void k3_fin(float* __restrict__ out) {
    int g = blockIdx.x * 256 + threadIdx.x;   // float4 index
    int row = g >> 4;
    float l = g_l[row] + g_l[B * N + row];
    float inv = (l > 0.f) ? (1.f / l) : 0.f;
    float4 a = ((const float4*)g_acc)[g];
    float4 c = ((const float4*)g_acc)[TOT4 + g];
    float v[4] = {(a.x + c.x) * inv, (a.y + c.y) * inv,
                  (a.z + c.z) * inv, (a.w + c.w) * inv};
#pragma unroll
    for (int q = 0; q < 4; ++q) v[q] = v[q] > 0.f ? v[q] : expm1f(v[q]);
    ((float4*)out)[g] = make_float4(v[0], v[1], v[2], v[3]);
}

// ---------------------------------------------------------------------------
extern "C" void kernel_launch(void* const* d_in, const int* in_sizes, int n_in,
                              void* d_out, int out_size) {
    const float* x   = (const float*)d_in[0];
    const int*   adj = (const int*)d_in[1];
    const float* W   = (const float*)d_in[2];
    const float* w2  = (const float*)d_in[3];
    float* out = (float*)d_out;

    k1_proj<<<(B * N) / 32, 256>>>(x, W, w2);
    dim3 g2(N / TI, B, SPLIT);
    k2_attn<<<g2, 256>>>(adj);
    k3_fin<<<TOT4 / 256, 256>>>(out);
}

// round 17
// speedup vs baseline: 1.3825x; 1.3825x over previous
#include <cuda_runtime.h>
#include <math.h>

#define B 8
#define N 2048
#define FIN 128
#define FOUT 64
#define ALPHA 0.2f

#define TI 128
#define TJ 64
#define SPLIT 4
#define JTILES ((N / SPLIT) / TJ)   // 8

typedef unsigned long long u64;

// Scratch (allocation-free rule: device globals)
__device__ float g_wh[B * N * FOUT];                 // 4 MB
__device__ float g_s1[B * N];
__device__ float g_s2[B * N];
__device__ float g_acc[SPLIT * B * N * FOUT];        // 16 MB partials
__device__ float g_l[SPLIT * B * N];                 // partial row sums

__device__ __forceinline__ u64 bcast2(float v) {
    u64 r;
    asm("mov.b64 %0, {%1, %1};" : "=l"(r) : "r"(__float_as_uint(v)));
    return r;
}
__device__ __forceinline__ u64 pack2(float a, float b) {
    u64 r;
    asm("mov.b64 %0, {%1, %2};" : "=l"(r) : "r"(__float_as_uint(a)), "r"(__float_as_uint(b)));
    return r;
}
__device__ __forceinline__ void fma2(u64& acc, u64 a, u64 b) {
    asm("fma.rn.f32x2 %0, %1, %2, %0;" : "+l"(acc) : "l"(a), "l"(b));
}
__device__ __forceinline__ void add2(u64& acc, u64 a) {
    asm("add.rn.f32x2 %0, %1, %0;" : "+l"(acc) : "l"(a));
}
__device__ __forceinline__ float lo2(u64 v) { return __uint_as_float((unsigned)(v & 0xffffffffu)); }
__device__ __forceinline__ float hi2(u64 v) { return __uint_as_float((unsigned)(v >> 32)); }

// ---------------------------------------------------------------------------
// K1: wh = x @ W ; s1 = wh @ a1 ; s2 = wh @ a2.
// 64 rows / block, W (32KB) + x tile (33KB) in dynamic smem.
// Thread = 2 rows x 8 cols. All smem accesses conflict-free.
// ---------------------------------------------------------------------------
#define K1_ROWS 64
#define XS_STRIDE 132
#define K1_SMEM (FIN * FOUT * 4 + K1_ROWS * XS_STRIDE * 4)   // 32768 + 33792

__global__ __launch_bounds__(256) void k1_proj(const float* __restrict__ x,
                                               const float* __restrict__ W,
                                               const float* __restrict__ w2) {
    extern __shared__ float sm1[];
    float* Ws = sm1;                         // [128][64]
    float* xs = sm1 + FIN * FOUT;            // [64][132]

    int t = threadIdx.x;
    int row0 = blockIdx.x * K1_ROWS;

#pragma unroll
    for (int q = 0; q < 8; ++q) {
        int lin = t + q * 256;               // 2048 float4s of W
        ((float4*)Ws)[lin] = ((const float4*)W)[lin];
    }
#pragma unroll
    for (int q = 0; q < 8; ++q) {
        int lin = t + q * 256;               // 64 rows x 32 float4
        int r = lin >> 5, c = lin & 31;
        float4 v = *(const float4*)&x[(size_t)(row0 + r) * FIN + c * 4];
        *(float4*)&xs[r * XS_STRIDE + c * 4] = v;
    }
    __syncthreads();

    int cg = t & 7, rg = t >> 3;             // rg 0..31 -> rows 2rg, 2rg+1
    int c1 = cg * 4, c2 = 32 + cg * 4;
    const float* x0p = xs + (2 * rg) * XS_STRIDE;
    const float* x1p = x0p + XS_STRIDE;

    u64 acc[2][4];
#pragma unroll
    for (int r = 0; r < 2; ++r)
#pragma unroll
        for (int q = 0; q < 4; ++q) acc[r][q] = 0ull;

#pragma unroll 4
    for (int k = 0; k < FIN; ++k) {
        u64 xx0 = bcast2(x0p[k]);
        u64 xx1 = bcast2(x1p[k]);
        ulonglong2 wa = *(const ulonglong2*)&Ws[k * FOUT + c1];
        ulonglong2 wb = *(const ulonglong2*)&Ws[k * FOUT + c2];
        fma2(acc[0][0], wa.x, xx0); fma2(acc[0][1], wa.y, xx0);
        fma2(acc[0][2], wb.x, xx0); fma2(acc[0][3], wb.y, xx0);
        fma2(acc[1][0], wa.x, xx1); fma2(acc[1][1], wa.y, xx1);
        fma2(acc[1][2], wb.x, xx1); fma2(acc[1][3], wb.y, xx1);
    }

    float4 a1a = *(const float4*)&w2[c1];
    float4 a1b = *(const float4*)&w2[c2];
    float4 a2a = *(const float4*)&w2[FOUT + c1];
    float4 a2b = *(const float4*)&w2[FOUT + c2];

#pragma unroll
    for (int r = 0; r < 2; ++r) {
        int row = row0 + 2 * rg + r;
        float wv[8];
        wv[0] = lo2(acc[r][0]); wv[1] = hi2(acc[r][0]);
        wv[2] = lo2(acc[r][1]); wv[3] = hi2(acc[r][1]);
        wv[4] = lo2(acc[r][2]); wv[5] = hi2(acc[r][2]);
        wv[6] = lo2(acc[r][3]); wv[7] = hi2(acc[r][3]);
        *(float4*)&g_wh[(size_t)row * FOUT + c1] = make_float4(wv[0], wv[1], wv[2], wv[3]);
        *(float4*)&g_wh[(size_t)row * FOUT + c2] = make_float4(wv[4], wv[5], wv[6], wv[7]);

        float p1 = wv[0]*a1a.x + wv[1]*a1a.y + wv[2]*a1a.z + wv[3]*a1a.w
                 + wv[4]*a1b.x + wv[5]*a1b.y + wv[6]*a1b.z + wv[7]*a1b.w;
        float p2 = wv[0]*a2a.x + wv[1]*a2a.y + wv[2]*a2a.z + wv[3]*a2a.w
                 + wv[4]*a2b.x + wv[5]*a2b.y + wv[6]*a2b.z + wv[7]*a2b.w;
#pragma unroll
        for (int off = 4; off > 0; off >>= 1) {
            p1 += __shfl_xor_sync(0xffffffffu, p1, off);
            p2 += __shfl_xor_sync(0xffffffffu, p2, off);
        }
        if (cg == 0) { g_s1[row] = p1; g_s2[row] = p2; }
    }
}

// ---------------------------------------------------------------------------
// K2: fused flash-GAT, TI=128. Unnormalized p = adj * exp(leakyrelu(s1+s2))
// (scores bounded, no max-shift needed). acc = sum p*wh, l = sum p, one pass.
// Thread = 4 rows x 8 cols in accumulate. p stored rowgroup-major as float4:
// score STS.128 conflict-free, accumulate LDS.128 1 wavefront per j.
// ---------------------------------------------------------------------------
#define P4_STRIDE 66                           // float4 units, bank-staggered
#define WH_STRIDE 68
#define SM2_P4    (32 * P4_STRIDE * 16)        // 33792 B
#define SM2_WH    (TJ * WH_STRIDE * 4)         // 17408 B
#define K2_SMEM   (SM2_P4 + SM2_WH + TI * 4 + TJ * 4)

__global__ __launch_bounds__(256, 2) void k2_attn(const int* __restrict__ adj) {
    extern __shared__ float sm2[];
    float4* p4  = (float4*)sm2;                          // [32][66]
    float*  wh_s = sm2 + SM2_P4 / 4;                     // [64][68]
    float*  s1_s = wh_s + SM2_WH / 4;                    // [128]
    float*  s2_s = s1_s + TI;                            // [64]

    int t = threadIdx.x;
    int b = blockIdx.y;
    int i0 = blockIdx.x * TI;
    int z = blockIdx.z;
    int jbase = z * (N / SPLIT);

    const int* adjb = adj + (size_t)b * N * N;
    const float* whb = g_wh + (size_t)b * N * FOUT;

    int cg = t & 7, rg = t >> 3;             // rows 4rg..4rg+3
    int c1 = cg * 4, c2 = 32 + cg * 4;
    int iq = t >> 6, jq = t & 63;            // score role: rows iq*32+q, col jq

    if (t < TI) s1_s[t] = g_s1[b * N + i0 + t];

    u64 acc[4][4];
#pragma unroll
    for (int r = 0; r < 4; ++r)
#pragma unroll
        for (int q = 0; q < 4; ++q) acc[r][q] = 0ull;
    u64 l01 = 0ull, l23 = 0ull;

    // adj column pointer for this thread's (iq, jq)
    const int* aptr = adjb + (size_t)(i0 + iq * 32) * N + jbase + jq;
    int areg[16];                            // rows 0..15 of this thread's 32
#pragma unroll
    for (int q = 0; q < 16; ++q) areg[q] = aptr[(size_t)q * N];

    for (int jt = 0; jt < JTILES; ++jt) {
        int j0 = jbase + jt * TJ;

        __syncthreads();   // prev accumulate done with p4/wh_s (covers s1_s @jt=0)
#pragma unroll
        for (int q = 0; q < 4; ++q) {
            int lin = t + q * 256;           // 64 rows x 16 float4
            int row = lin >> 4;
            int c4 = (lin & 15) * 4;
            *(float4*)&wh_s[row * WH_STRIDE + c4] =
                *(const float4*)&whb[(size_t)(j0 + row) * FOUT + c4];
        }
        if (t < TJ) s2_s[t] = g_s2[b * N + j0 + t];
        __syncthreads();

        // issue direct adj loads for rows 16..31 (hidden behind first-half work)
        const int* ap = aptr + jt * TJ;
        int a2[16];
#pragma unroll
        for (int q = 0; q < 16; ++q) a2[q] = ap[(size_t)(16 + q) * N];

        float s2v = s2_s[jq];
        // rows 0..15 from prefetch
#pragma unroll
        for (int c = 0; c < 4; ++c) {
            float pv[4];
#pragma unroll
            for (int d = 0; d < 4; ++d) {
                float tt = s1_s[iq * 32 + c * 4 + d] + s2v;
                float lk = fmaxf(tt, ALPHA * tt);
                pv[d] = __expf(lk) * (float)areg[c * 4 + d];   // adj in {0,1}
            }
            p4[(8 * iq + c) * P4_STRIDE + jq] = make_float4(pv[0], pv[1], pv[2], pv[3]);
        }
        // rows 16..31 from direct loads
#pragma unroll
        for (int c = 4; c < 8; ++c) {
            float pv[4];
#pragma unroll
            for (int d = 0; d < 4; ++d) {
                float tt = s1_s[iq * 32 + c * 4 + d] + s2v;
                float lk = fmaxf(tt, ALPHA * tt);
                pv[d] = __expf(lk) * (float)a2[(c - 4) * 4 + d];
            }
            p4[(8 * iq + c) * P4_STRIDE + jq] = make_float4(pv[0], pv[1], pv[2], pv[3]);
        }

        // prefetch next tile rows 0..15 (lands during accumulate)
        if (jt + 1 < JTILES) {
            const int* apn = aptr + (jt + 1) * TJ;
#pragma unroll
            for (int q = 0; q < 16; ++q) areg[q] = apn[(size_t)q * N];
        }
        __syncthreads();

        // accumulate: per j per warp = 3 LDS wavefronts, 18 fma-pipe ops
        const float4* prow = p4 + rg * P4_STRIDE;
#pragma unroll 8
        for (int j = 0; j < TJ; ++j) {
            float4 pv = prow[j];
            ulonglong2 wa = *(const ulonglong2*)&wh_s[j * WH_STRIDE + c1];
            ulonglong2 wb = *(const ulonglong2*)&wh_s[j * WH_STRIDE + c2];
            u64 pp0 = bcast2(pv.x), pp1 = bcast2(pv.y);
            u64 pp2 = bcast2(pv.z), pp3 = bcast2(pv.w);
            fma2(acc[0][0], wa.x, pp0); fma2(acc[0][1], wa.y, pp0);
            fma2(acc[0][2], wb.x, pp0); fma2(acc[0][3], wb.y, pp0);
            fma2(acc[1][0], wa.x, pp1); fma2(acc[1][1], wa.y, pp1);
            fma2(acc[1][2], wb.x, pp1); fma2(acc[1][3], wb.y, pp1);
            fma2(acc[2][0], wa.x, pp2); fma2(acc[2][1], wa.y, pp2);
            fma2(acc[2][2], wb.x, pp2); fma2(acc[2][3], wb.y, pp2);
            fma2(acc[3][0], wa.x, pp3); fma2(acc[3][1], wa.y, pp3);
            fma2(acc[3][2], wb.x, pp3); fma2(acc[3][3], wb.y, pp3);
            add2(l01, pack2(pv.x, pv.y));
            add2(l23, pack2(pv.z, pv.w));
        }
    }

    // epilogue: write partials
    size_t pbase = ((size_t)z * (B * N) + (size_t)b * N) * FOUT;
#pragma unroll
    for (int r = 0; r < 4; ++r) {
        int i = i0 + rg * 4 + r;
        *(float4*)&g_acc[pbase + (size_t)i * FOUT + c1] =
            make_float4(lo2(acc[r][0]), hi2(acc[r][0]), lo2(acc[r][1]), hi2(acc[r][1]));
        *(float4*)&g_acc[pbase + (size_t)i * FOUT + c2] =
            make_float4(lo2(acc[r][2]), hi2(acc[r][2]), lo2(acc[r][3]), hi2(acc[r][3]));
    }
    if (cg == 0) {
        size_t lb = (size_t)z * (B * N) + b * N + i0 + rg * 4;
        g_l[lb]     = lo2(l01);
        g_l[lb + 1] = hi2(l01);
        g_l[lb + 2] = lo2(l23);
        g_l[lb + 3] = hi2(l23);
    }
}

// ---------------------------------------------------------------------------
// K3: combine SPLIT partials, normalize, ELU.
// ---------------------------------------------------------------------------
#define TOT4 (B * N * FOUT / 4)   // 262144 float4s per split
__global__ __launch_bounds__(256) void k3_fin(float* __restrict__ out) {
    int g = blockIdx.x * 256 + threadIdx.x;   // float4 index
    int row = g >> 4;
    float l = 0.f;
    float v[4] = {0.f, 0.f, 0.f, 0.f};
#pragma unroll
    for (int z = 0; z < SPLIT; ++z) {
        l += g_l[(size_t)z * (B * N) + row];
        float4 a = ((const float4*)g_acc)[(size_t)z * TOT4 + g];
        v[0] += a.x; v[1] += a.y; v[2] += a.z; v[3] += a.w;
    }
    float inv = (l > 0.f) ? (1.f / l) : 0.f;
#pragma unroll
    for (int q = 0; q < 4; ++q) {
        float u = v[q] * inv;
        v[q] = u > 0.f ? u : expm1f(u);
    }
    ((float4*)out)[g] = make_float4(v[0], v[1], v[2], v[3]);
}

// ---------------------------------------------------------------------------
extern "C" void kernel_launch(void* const* d_in, const int* in_sizes, int n_in,
                              void* d_out, int out_size) {
    const float* x   = (const float*)d_in[0];
    const int*   adj = (const int*)d_in[1];
    const float* W   = (const float*)d_in[2];
    const float* w2  = (const float*)d_in[3];
    float* out = (float*)d_out;

    cudaFuncSetAttribute(k1_proj, cudaFuncAttributeMaxDynamicSharedMemorySize, K1_SMEM);
    cudaFuncSetAttribute(k2_attn, cudaFuncAttributeMaxDynamicSharedMemorySize, K2_SMEM);

    k1_proj<<<(B * N) / K1_ROWS, 256, K1_SMEM>>>(x, W, w2);
    dim3 g2(N / TI, B, SPLIT);
    k2_attn<<<g2, 256, K2_SMEM>>>(adj);
    k3_fin<<<TOT4 / 256, 256>>>(out);
}